// round 2
// baseline (speedup 1.0000x reference)
#include <cuda_runtime.h>
#include <cuda_bf16.h>
#include <mma.h>

using namespace nvcuda;

#define Bsz 64
#define Ssz 64
#define Hsz 1024
#define Vsz 32000
#define Tsz 40

// ---------------- scratch (static device allocations, allowed) ----------------
__device__ float g_keysU[Bsz * Ssz * Hsz];          // 16 MB, includes ba+bu bias
__device__ float g_emb[Tsz * Bsz * Hsz];            // 10 MB  [t][b][h]
__device__ float g_h[Bsz * Hsz];                    // current hidden
__device__ float g_q[Bsz * Hsz];                    // h @ Wa^T
__device__ float g_x[Bsz * 2 * Hsz];                // [emb | ctx]
__device__ float g_gi[Bsz * 3 * Hsz];
__device__ float g_gh[Bsz * 3 * Hsz];
__device__ __nv_bfloat16 g_hall[Tsz * Bsz * Hsz];   // 5 MB, all h_t in bf16
__device__ __nv_bfloat16 g_wout[Vsz * Hsz];         // 65 MB, W_out in bf16

// ---------------- init kernels ----------------
__global__ void k_init_h(const float* __restrict__ eh) {
    int i = blockIdx.x * blockDim.x + threadIdx.x;
    if (i < Bsz * Hsz) g_h[i] = eh[i];
}

__global__ void k_embed(const int* __restrict__ target, const float* __restrict__ emb) {
    int t = blockIdx.x / Bsz, b = blockIdx.x % Bsz;
    int tok = (t == 0) ? 0 : target[b * Tsz + t - 1];
    const float4* src = (const float4*)(emb + (size_t)tok * Hsz);
    float4* dst = (float4*)(g_emb + ((size_t)t * Bsz + b) * Hsz);
    for (int j = threadIdx.x; j < Hsz / 4; j += blockDim.x) dst[j] = src[j];
}

__global__ void k_wout_conv(const float* __restrict__ W) {
    int n4 = Vsz * Hsz / 4;
    for (int i = blockIdx.x * blockDim.x + threadIdx.x; i < n4; i += gridDim.x * blockDim.x) {
        float4 v = ((const float4*)W)[i];
        __nv_bfloat162 lo = __floats2bfloat162_rn(v.x, v.y);
        __nv_bfloat162 hi = __floats2bfloat162_rn(v.z, v.w);
        ((__nv_bfloat162*)g_wout)[2 * i] = lo;
        ((__nv_bfloat162*)g_wout)[2 * i + 1] = hi;
    }
}

__global__ void k_keysu_bias(const float* __restrict__ ba, const float* __restrict__ bu) {
    int total = Bsz * Ssz * Hsz;
    for (int i = blockIdx.x * blockDim.x + threadIdx.x; i < total; i += gridDim.x * blockDim.x) {
        int n = i & (Hsz - 1);
        g_keysU[i] += ba[n] + bu[n];
    }
}

// ---------------- generic TF32 wmma GEMM:  C[m,n] = sum_k A[m,k]*B[n,k] ----------------
// block = 128 threads (4 warps), block tile 64(m) x 64(n)
__device__ __forceinline__ void gemm64_body(const float* __restrict__ A,
                                            const float* __restrict__ B,
                                            float* __restrict__ C,
                                            int N, int K, int m0, int n0) {
    int warp = threadIdx.x >> 5;
    int mrow = m0 + warp * 16;
    wmma::fragment<wmma::accumulator, 16, 16, 8, float> acc[4];
#pragma unroll
    for (int j = 0; j < 4; j++) wmma::fill_fragment(acc[j], 0.0f);

    for (int k = 0; k < K; k += 8) {
        wmma::fragment<wmma::matrix_a, 16, 16, 8, wmma::precision::tf32, wmma::row_major> af;
        wmma::load_matrix_sync(af, A + (size_t)mrow * K + k, K);
#pragma unroll
        for (int e = 0; e < af.num_elements; e++) af.x[e] = wmma::__float_to_tf32(af.x[e]);
#pragma unroll
        for (int j = 0; j < 4; j++) {
            wmma::fragment<wmma::matrix_b, 16, 16, 8, wmma::precision::tf32, wmma::col_major> bf;
            wmma::load_matrix_sync(bf, B + (size_t)(n0 + j * 16) * K + k, K);
#pragma unroll
            for (int e = 0; e < bf.num_elements; e++) bf.x[e] = wmma::__float_to_tf32(bf.x[e]);
            wmma::mma_sync(acc[j], af, bf, acc[j]);
        }
    }
#pragma unroll
    for (int j = 0; j < 4; j++)
        wmma::store_matrix_sync(C + (size_t)mrow * N + n0 + j * 16, acc[j], N, wmma::mem_row_major);
}

__global__ __launch_bounds__(128) void k_gemm_tf32(const float* A, const float* B, float* C,
                                                   int N, int K) {
    gemm64_body(A, B, C, N, K, blockIdx.y * 64, blockIdx.x * 64);
}

// gi = x @ W_ih^T  (48 blocks)  |  gh = h @ W_hh^T  (48 blocks)  in one launch
__global__ __launch_bounds__(128) void k_gemm_gru(const float* __restrict__ Wih,
                                                  const float* __restrict__ Whh) {
    if (blockIdx.x < 48)
        gemm64_body(g_x, Wih, g_gi, 3 * Hsz, 2 * Hsz, 0, blockIdx.x * 64);
    else
        gemm64_body(g_h, Whh, g_gh, 3 * Hsz, Hsz, 0, (blockIdx.x - 48) * 64);
}

// ---------------- attention: scores + softmax + ctx + build x ----------------
__global__ __launch_bounds__(256) void k_attn(int t, const float* __restrict__ enc,
                                              const float* __restrict__ Va,
                                              float* __restrict__ out_attn) {
    int b = blockIdx.x;
    __shared__ float qs[Hsz];
    __shared__ float va[Hsz];
    __shared__ float sc[Ssz];
    __shared__ float ws[Ssz];
    int tid = threadIdx.x;
    for (int j = tid; j < Hsz; j += 256) { qs[j] = g_q[b * Hsz + j]; va[j] = Va[j]; }
    __syncthreads();

    int w = tid >> 5, lane = tid & 31;
    for (int si = 0; si < 8; si++) {
        int s = w * 8 + si;
        const float* kp = g_keysU + (size_t)(b * Ssz + s) * Hsz;
        float p = 0.f;
        for (int j = lane; j < Hsz; j += 32) p += va[j] * tanhf(qs[j] + kp[j]);
#pragma unroll
        for (int o = 16; o > 0; o >>= 1) p += __shfl_xor_sync(0xffffffffu, p, o);
        if (lane == 0) sc[s] = p;
    }
    __syncthreads();

    if (w == 0) {  // softmax over 64 scores (bv dropped: shift-invariant)
        float v0 = sc[lane], v1 = sc[lane + 32];
        float m = fmaxf(v0, v1);
#pragma unroll
        for (int o = 16; o > 0; o >>= 1) m = fmaxf(m, __shfl_xor_sync(0xffffffffu, m, o));
        float e0 = __expf(v0 - m), e1 = __expf(v1 - m);
        float ssum = e0 + e1;
#pragma unroll
        for (int o = 16; o > 0; o >>= 1) ssum += __shfl_xor_sync(0xffffffffu, ssum, o);
        float inv = 1.f / ssum;
        ws[lane] = e0 * inv;
        ws[lane + 32] = e1 * inv;
    }
    __syncthreads();

    for (int j = tid; j < Hsz; j += 256) {
        float c = 0.f;
#pragma unroll 8
        for (int s = 0; s < Ssz; s++) c += ws[s] * enc[(size_t)(b * Ssz + s) * Hsz + j];
        g_x[b * 2 * Hsz + Hsz + j] = c;                                  // ctx
        g_x[b * 2 * Hsz + j] = g_emb[((size_t)t * Bsz + b) * Hsz + j];   // emb
    }
    if (tid < Ssz) out_attn[(size_t)b * Tsz * Ssz + t * Ssz + tid] = ws[tid];
}

// ---------------- GRU gates + h update ----------------
__global__ __launch_bounds__(256) void k_gates(int t, const float* __restrict__ b_ih,
                                               const float* __restrict__ b_hh) {
    int b = blockIdx.x, tid = threadIdx.x;
    for (int j = tid; j < Hsz; j += 256) {
        float ir = g_gi[b * 3 * Hsz + j]            + b_ih[j];
        float iz = g_gi[b * 3 * Hsz + Hsz + j]      + b_ih[Hsz + j];
        float in = g_gi[b * 3 * Hsz + 2 * Hsz + j]  + b_ih[2 * Hsz + j];
        float hr = g_gh[b * 3 * Hsz + j]            + b_hh[j];
        float hz = g_gh[b * 3 * Hsz + Hsz + j]      + b_hh[Hsz + j];
        float hn = g_gh[b * 3 * Hsz + 2 * Hsz + j]  + b_hh[2 * Hsz + j];
        float r = 1.f / (1.f + __expf(-(ir + hr)));
        float z = 1.f / (1.f + __expf(-(iz + hz)));
        float n = tanhf(in + r * hn);
        float hp = g_h[b * Hsz + j];
        float hnew = (1.f - z) * n + z * hp;
        g_h[b * Hsz + j] = hnew;
        g_hall[((size_t)t * Bsz + b) * Hsz + j] = __float2bfloat16(hnew);
    }
}

// ---------------- batched output projection: logits = Hall @ Wout^T + b_out ----------------
// bf16 wmma, block tile 128x128, BK=32, 8 warps (2x4), double-buffered smem
__global__ __launch_bounds__(256) void k_gemm_out(const float* __restrict__ b_out,
                                                  float* __restrict__ out) {
    const int K = Hsz;
    __shared__ __nv_bfloat16 As[2][128 * 40];
    __shared__ __nv_bfloat16 Bs[2][128 * 40];
    int m0 = blockIdx.y * 128, n0 = blockIdx.x * 128;
    int tid = threadIdx.x;
    int warp = tid >> 5, lane = tid & 31;
    int wm = warp >> 2, wn = warp & 3;
    int lrow = tid >> 2;
    int kch = (tid & 3) * 8;

    wmma::fragment<wmma::accumulator, 16, 16, 16, float> acc[4][2];
#pragma unroll
    for (int i = 0; i < 4; i++)
#pragma unroll
        for (int j = 0; j < 2; j++) wmma::fill_fragment(acc[i][j], 0.f);

    const __nv_bfloat16* Ag = g_hall + (size_t)(m0 + lrow) * K + kch;
    const __nv_bfloat16* Bg = g_wout + (size_t)(n0 + lrow) * K + kch;

    uint4 ra0, ra1, rb0, rb1;
    ra0 = *(const uint4*)(Ag);            ra1 = *(const uint4*)(Ag + 64 * K);
    rb0 = *(const uint4*)(Bg);            rb1 = *(const uint4*)(Bg + 64 * K);
    *(uint4*)&As[0][lrow * 40 + kch] = ra0;
    *(uint4*)&As[0][(lrow + 64) * 40 + kch] = ra1;
    *(uint4*)&Bs[0][lrow * 40 + kch] = rb0;
    *(uint4*)&Bs[0][(lrow + 64) * 40 + kch] = rb1;
    __syncthreads();

    const int NKT = K / 32;
    for (int kt = 0; kt < NKT; kt++) {
        int cur = kt & 1, nxt = cur ^ 1;
        if (kt + 1 < NKT) {
            const __nv_bfloat16* a = Ag + (kt + 1) * 32;
            ra0 = *(const uint4*)(a);     ra1 = *(const uint4*)(a + 64 * K);
            const __nv_bfloat16* bp = Bg + (kt + 1) * 32;
            rb0 = *(const uint4*)(bp);    rb1 = *(const uint4*)(bp + 64 * K);
        }
#pragma unroll
        for (int ks = 0; ks < 2; ks++) {
            wmma::fragment<wmma::matrix_a, 16, 16, 16, __nv_bfloat16, wmma::row_major> af[4];
            wmma::fragment<wmma::matrix_b, 16, 16, 16, __nv_bfloat16, wmma::col_major> bf[2];
#pragma unroll
            for (int i = 0; i < 4; i++)
                wmma::load_matrix_sync(af[i], &As[cur][(wm * 64 + i * 16) * 40 + ks * 16], 40);
#pragma unroll
            for (int j = 0; j < 2; j++)
                wmma::load_matrix_sync(bf[j], &Bs[cur][(wn * 32 + j * 16) * 40 + ks * 16], 40);
#pragma unroll
            for (int i = 0; i < 4; i++)
#pragma unroll
                for (int j = 0; j < 2; j++)
                    wmma::mma_sync(acc[i][j], af[i], bf[j], acc[i][j]);
        }
        if (kt + 1 < NKT) {
            *(uint4*)&As[nxt][lrow * 40 + kch] = ra0;
            *(uint4*)&As[nxt][(lrow + 64) * 40 + kch] = ra1;
            *(uint4*)&Bs[nxt][lrow * 40 + kch] = rb0;
            *(uint4*)&Bs[nxt][(lrow + 64) * 40 + kch] = rb1;
        }
        __syncthreads();
    }

    // epilogue: stage per-warp 16x16 tiles, remap rows (t*64+b) -> out[(b*T+t)*V]
    float* stage = (float*)&As[0][0];
    float* sp = stage + warp * 320;  // 16 * 20 per warp
#pragma unroll
    for (int i = 0; i < 4; i++) {
#pragma unroll
        for (int j = 0; j < 2; j++) {
            wmma::store_matrix_sync(sp, acc[i][j], 20, wmma::mem_row_major);
            __syncwarp();
            int gr0 = m0 + wm * 64 + i * 16;
            int gc0 = n0 + wn * 32 + j * 16;
            for (int e = lane; e < 256; e += 32) {
                int r = e >> 4, c = e & 15;
                int gr = gr0 + r, gc = gc0 + c;
                int bb = gr & 63, tt = gr >> 6;
                out[(size_t)(bb * Tsz + tt) * Vsz + gc] = sp[r * 20 + c] + b_out[gc];
            }
            __syncwarp();
        }
    }
}

// ---------------- in-place log_softmax over V per (b,t) row ----------------
__global__ __launch_bounds__(256) void k_logsoftmax(float* __restrict__ out) {
    int row = blockIdx.x;
    float* p = out + (size_t)row * Vsz;
    int tid = threadIdx.x;
    float m = -1e30f, s = 0.f;
    for (int j = tid; j < Vsz; j += 256) {
        float v = p[j];
        if (v > m) { s = s * __expf(m - v) + 1.f; m = v; }
        else       { s += __expf(v - m); }
    }
    __shared__ float sm[256], ss[256];
    sm[tid] = m; ss[tid] = s;
    __syncthreads();
    for (int o = 128; o > 0; o >>= 1) {
        if (tid < o) {
            float m2 = sm[tid + o], s2 = ss[tid + o];
            float mm = fmaxf(sm[tid], m2);
            ss[tid] = ss[tid] * __expf(sm[tid] - mm) + s2 * __expf(m2 - mm);
            sm[tid] = mm;
        }
        __syncthreads();
    }
    float L = sm[0] + logf(ss[0]);
    for (int j = tid; j < Vsz; j += 256) p[j] = p[j] - L;
}

__global__ void k_hidden(float* __restrict__ out) {
    int i = blockIdx.x * blockDim.x + threadIdx.x;
    if (i < Bsz * Hsz) out[i] = g_h[i];
}

// ---------------- launch ----------------
extern "C" void kernel_launch(void* const* d_in, const int* in_sizes, int n_in,
                              void* d_out, int out_size) {
    const float* enc_out = (const float*)d_in[0];
    const float* enc_hid = (const float*)d_in[1];
    const int*   target  = (const int*)d_in[2];
    const float* embedding = (const float*)d_in[3];
    const float* Wa  = (const float*)d_in[4];
    const float* ba  = (const float*)d_in[5];
    const float* Ua  = (const float*)d_in[6];
    const float* bu  = (const float*)d_in[7];
    const float* Va  = (const float*)d_in[8];
    // d_in[9] = bv : softmax shift-invariant, unused
    const float* W_ih = (const float*)d_in[10];
    const float* W_hh = (const float*)d_in[11];
    const float* b_ih = (const float*)d_in[12];
    const float* b_hh = (const float*)d_in[13];
    const float* W_out = (const float*)d_in[14];
    const float* b_out = (const float*)d_in[15];

    float* out = (float*)d_out;
    float* out_dec  = out;                                        // [B,T,V]
    float* out_hid  = out + (size_t)Bsz * Tsz * Vsz;              // [1,B,H]
    float* out_attn = out_hid + (size_t)Bsz * Hsz;                // [B,T,S]

    // --- init (once per replay) ---
    k_init_h<<<(Bsz * Hsz + 255) / 256, 256>>>(enc_hid);
    k_embed<<<Tsz * Bsz, 256>>>(target, embedding);
    {
        float* keysU = nullptr;  cudaGetSymbolAddress((void**)&keysU, g_keysU);
        dim3 grid(Hsz / 64, (Bsz * Ssz) / 64);
        k_gemm_tf32<<<grid, 128>>>(enc_out, Ua, keysU, Hsz, Hsz);
    }
    k_keysu_bias<<<4096, 256>>>(ba, bu);
    k_wout_conv<<<2048, 256>>>(W_out);

    // --- recurrence ---
    for (int t = 0; t < Tsz; t++) {
        {
            float* h = nullptr; cudaGetSymbolAddress((void**)&h, g_h);
            float* q = nullptr; cudaGetSymbolAddress((void**)&q, g_q);
            dim3 grid(Hsz / 64, 1);
            k_gemm_tf32<<<grid, 128>>>(h, Wa, q, Hsz, Hsz);
        }
        k_attn<<<Bsz, 256>>>(t, enc_out, Va, out_attn);
        k_gemm_gru<<<96, 128>>>(W_ih, W_hh);
        k_gates<<<Bsz, 256>>>(t, b_ih, b_hh);
    }

    // --- batched output projection + log_softmax + hidden ---
    {
        dim3 grid(Vsz / 128, (Tsz * Bsz) / 128);  // 250 x 20
        k_gemm_out<<<grid, 256>>>(b_out, out_dec);
    }
    k_logsoftmax<<<Tsz * Bsz, 256>>>(out_dec);
    k_hidden<<<(Bsz * Hsz + 255) / 256, 256>>>(out_hid);
}

// round 3
// speedup vs baseline: 3.1311x; 3.1311x over previous
#include <cuda_runtime.h>
#include <cuda_bf16.h>
#include <mma.h>

using namespace nvcuda;

#define Bsz 64
#define Ssz 64
#define Hsz 1024
#define Vsz 32000
#define Tsz 40

// ---------------- scratch (static device allocations, allowed) ----------------
__device__ float g_keysU[Bsz * Ssz * Hsz];          // 16 MB, includes ba+bu bias
__device__ float g_emb[Tsz * Bsz * Hsz];            // 10 MB  [t][b][h]
__device__ float g_h[Bsz * Hsz];                    // current hidden
__device__ float g_q[Bsz * Hsz];                    // h @ Wa^T
__device__ float g_x[Bsz * 2 * Hsz];                // [emb | ctx]
__device__ float g_gi[Bsz * 3 * Hsz];
__device__ float g_gh[Bsz * 3 * Hsz];
__device__ __nv_bfloat16 g_hall[Tsz * Bsz * Hsz];   // 5 MB, all h_t in bf16
__device__ __nv_bfloat16 g_wout[Vsz * Hsz];         // 65 MB, W_out in bf16

// fast activations
__device__ __forceinline__ float ftanh(float x) {
    float e = __expf(2.f * x);
    return 1.f - __fdividef(2.f, e + 1.f);
}
__device__ __forceinline__ float fsigmoid(float x) {
    return __fdividef(1.f, 1.f + __expf(-x));
}

// ---------------- init kernels ----------------
__global__ void k_init_h(const float* __restrict__ eh) {
    int i = blockIdx.x * blockDim.x + threadIdx.x;
    if (i < Bsz * Hsz) g_h[i] = eh[i];
}

__global__ void k_embed(const int* __restrict__ target, const float* __restrict__ emb) {
    int t = blockIdx.x / Bsz, b = blockIdx.x % Bsz;
    int tok = (t == 0) ? 0 : target[b * Tsz + t - 1];
    const float4* src = (const float4*)(emb + (size_t)tok * Hsz);
    float4* dst = (float4*)(g_emb + ((size_t)t * Bsz + b) * Hsz);
    for (int j = threadIdx.x; j < Hsz / 4; j += blockDim.x) dst[j] = src[j];
}

__global__ void k_wout_conv(const float* __restrict__ W) {
    int n4 = Vsz * Hsz / 4;
    for (int i = blockIdx.x * blockDim.x + threadIdx.x; i < n4; i += gridDim.x * blockDim.x) {
        float4 v = ((const float4*)W)[i];
        __nv_bfloat162 lo = __floats2bfloat162_rn(v.x, v.y);
        __nv_bfloat162 hi = __floats2bfloat162_rn(v.z, v.w);
        ((__nv_bfloat162*)g_wout)[2 * i] = lo;
        ((__nv_bfloat162*)g_wout)[2 * i + 1] = hi;
    }
}

__global__ void k_keysu_bias(const float* __restrict__ ba, const float* __restrict__ bu) {
    int total = Bsz * Ssz * Hsz;
    for (int i = blockIdx.x * blockDim.x + threadIdx.x; i < total; i += gridDim.x * blockDim.x) {
        int n = i & (Hsz - 1);
        g_keysU[i] += ba[n] + bu[n];
    }
}

// ---------------- tf32 GEMM, smem-staged, double-buffered ----------------
// C[m0:m0+64, n0:n0+64] = A[m0:m0+64, 0:K] @ B[n0:n0+64, 0:K]^T
// block = 256 threads (8 warps: 4m x 2n), BK = 32
__device__ __forceinline__ void gemm_body(const float* __restrict__ A,
                                          const float* __restrict__ B,
                                          float* __restrict__ C,
                                          int K, int ldc, int m0, int n0) {
    __shared__ float As[2][64][36];
    __shared__ float Bs[2][64][36];
    int tid = threadIdx.x;
    int r = tid >> 3;               // 0..31
    int c = (tid & 7) * 4;          // 0..28
    int warp = tid >> 5;
    int wm = warp >> 1;             // 0..3
    int wn = warp & 1;              // 0..1

    wmma::fragment<wmma::accumulator, 16, 16, 8, float> acc[2];
#pragma unroll
    for (int j = 0; j < 2; j++) wmma::fill_fragment(acc[j], 0.0f);

    const float* Ap = A + (size_t)(m0 + r) * K + c;
    const float* Bp = B + (size_t)(n0 + r) * K + c;

    float4 a0 = *(const float4*)Ap;
    float4 a1 = *(const float4*)(Ap + 32 * (size_t)K);
    float4 b0 = *(const float4*)Bp;
    float4 b1 = *(const float4*)(Bp + 32 * (size_t)K);
    *(float4*)&As[0][r][c] = a0;  *(float4*)&As[0][r + 32][c] = a1;
    *(float4*)&Bs[0][r][c] = b0;  *(float4*)&Bs[0][r + 32][c] = b1;
    __syncthreads();

    int NIT = K >> 5;
    for (int it = 0; it < NIT; it++) {
        int cur = it & 1, nxt = cur ^ 1;
        if (it + 1 < NIT) {
            const float* Ap2 = Ap + (it + 1) * 32;
            const float* Bp2 = Bp + (it + 1) * 32;
            a0 = *(const float4*)Ap2;
            a1 = *(const float4*)(Ap2 + 32 * (size_t)K);
            b0 = *(const float4*)Bp2;
            b1 = *(const float4*)(Bp2 + 32 * (size_t)K);
            *(float4*)&As[nxt][r][c] = a0;  *(float4*)&As[nxt][r + 32][c] = a1;
            *(float4*)&Bs[nxt][r][c] = b0;  *(float4*)&Bs[nxt][r + 32][c] = b1;
        }
#pragma unroll
        for (int ks = 0; ks < 4; ks++) {
            wmma::fragment<wmma::matrix_a, 16, 16, 8, wmma::precision::tf32, wmma::row_major> af;
            wmma::load_matrix_sync(af, &As[cur][wm * 16][ks * 8], 36);
#pragma unroll
            for (int e = 0; e < af.num_elements; e++) af.x[e] = wmma::__float_to_tf32(af.x[e]);
#pragma unroll
            for (int j = 0; j < 2; j++) {
                wmma::fragment<wmma::matrix_b, 16, 16, 8, wmma::precision::tf32, wmma::col_major> bf;
                wmma::load_matrix_sync(bf, &Bs[cur][wn * 32 + j * 16][ks * 8], 36);
#pragma unroll
                for (int e = 0; e < bf.num_elements; e++) bf.x[e] = wmma::__float_to_tf32(bf.x[e]);
                wmma::mma_sync(acc[j], af, bf, acc[j]);
            }
        }
        __syncthreads();
    }
#pragma unroll
    for (int j = 0; j < 2; j++)
        wmma::store_matrix_sync(C + (size_t)(m0 + wm * 16) * ldc + n0 + wn * 32 + j * 16,
                                acc[j], ldc, wmma::mem_row_major);
}

// keysU = enc @ Ua^T  : M = B*S = 4096 (grid.y), N = 1024 (grid.x)
__global__ __launch_bounds__(256) void k_gemm_keysu(const float* __restrict__ enc,
                                                    const float* __restrict__ Ua,
                                                    float* __restrict__ outC) {
    gemm_body(enc, Ua, outC, Hsz, Hsz, blockIdx.y * 64, blockIdx.x * 64);
}

// q = h @ Wa^T : 16 blocks
__global__ __launch_bounds__(256) void k_gemm_q(const float* __restrict__ Wa) {
    gemm_body(g_h, Wa, g_q, Hsz, Hsz, 0, blockIdx.x * 64);
}

// gi = x @ W_ih^T (48 blocks) | gh = h @ W_hh^T (48 blocks)
__global__ __launch_bounds__(256) void k_gemm_gru(const float* __restrict__ Wih,
                                                  const float* __restrict__ Whh) {
    if (blockIdx.x < 48)
        gemm_body(g_x, Wih, g_gi, 2 * Hsz, 3 * Hsz, 0, blockIdx.x * 64);
    else
        gemm_body(g_h, Whh, g_gh, Hsz, 3 * Hsz, 0, (blockIdx.x - 48) * 64);
}

// ---------------- attention: scores + softmax + ctx + build x ----------------
__global__ __launch_bounds__(256) void k_attn(int t, const float* __restrict__ enc,
                                              const float* __restrict__ Va,
                                              float* __restrict__ out_attn) {
    int b = blockIdx.x;
    __shared__ float qs[Hsz];
    __shared__ float va[Hsz];
    __shared__ float sc[Ssz];
    __shared__ float ws[Ssz];
    int tid = threadIdx.x;
    for (int j = tid; j < Hsz; j += 256) { qs[j] = g_q[b * Hsz + j]; va[j] = Va[j]; }
    __syncthreads();

    int w = tid >> 5, lane = tid & 31;
    for (int si = 0; si < 8; si++) {
        int s = w * 8 + si;
        const float* kp = g_keysU + (size_t)(b * Ssz + s) * Hsz;
        float p = 0.f;
#pragma unroll 4
        for (int j = lane; j < Hsz; j += 32) p += va[j] * ftanh(qs[j] + kp[j]);
#pragma unroll
        for (int o = 16; o > 0; o >>= 1) p += __shfl_xor_sync(0xffffffffu, p, o);
        if (lane == 0) sc[s] = p;
    }
    __syncthreads();

    if (w == 0) {  // softmax over 64 scores (bv dropped: shift-invariant)
        float v0 = sc[lane], v1 = sc[lane + 32];
        float m = fmaxf(v0, v1);
#pragma unroll
        for (int o = 16; o > 0; o >>= 1) m = fmaxf(m, __shfl_xor_sync(0xffffffffu, m, o));
        float e0 = __expf(v0 - m), e1 = __expf(v1 - m);
        float ssum = e0 + e1;
#pragma unroll
        for (int o = 16; o > 0; o >>= 1) ssum += __shfl_xor_sync(0xffffffffu, ssum, o);
        float inv = __fdividef(1.f, ssum);
        ws[lane] = e0 * inv;
        ws[lane + 32] = e1 * inv;
    }
    __syncthreads();

    for (int j = tid; j < Hsz; j += 256) {
        float cacc = 0.f;
#pragma unroll 8
        for (int s = 0; s < Ssz; s++) cacc += ws[s] * enc[(size_t)(b * Ssz + s) * Hsz + j];
        g_x[b * 2 * Hsz + Hsz + j] = cacc;                               // ctx
        g_x[b * 2 * Hsz + j] = g_emb[((size_t)t * Bsz + b) * Hsz + j];   // emb
    }
    if (tid < Ssz) out_attn[(size_t)b * Tsz * Ssz + t * Ssz + tid] = ws[tid];
}

// ---------------- GRU gates + h update ----------------
__global__ __launch_bounds__(256) void k_gates(int t, const float* __restrict__ b_ih,
                                               const float* __restrict__ b_hh) {
    int b = blockIdx.x, tid = threadIdx.x;
    for (int j = tid; j < Hsz; j += 256) {
        float ir = g_gi[b * 3 * Hsz + j]            + b_ih[j];
        float iz = g_gi[b * 3 * Hsz + Hsz + j]      + b_ih[Hsz + j];
        float in = g_gi[b * 3 * Hsz + 2 * Hsz + j]  + b_ih[2 * Hsz + j];
        float hr = g_gh[b * 3 * Hsz + j]            + b_hh[j];
        float hz = g_gh[b * 3 * Hsz + Hsz + j]      + b_hh[Hsz + j];
        float hn = g_gh[b * 3 * Hsz + 2 * Hsz + j]  + b_hh[2 * Hsz + j];
        float rr = fsigmoid(ir + hr);
        float zz = fsigmoid(iz + hz);
        float nn = ftanh(in + rr * hn);
        float hp = g_h[b * Hsz + j];
        float hnew = (1.f - zz) * nn + zz * hp;
        g_h[b * Hsz + j] = hnew;
        g_hall[((size_t)t * Bsz + b) * Hsz + j] = __float2bfloat16(hnew);
    }
}

// ---------------- batched output projection: logits = Hall @ Wout^T + b_out ----------------
// bf16 wmma, block tile 128x128, BK=32, 8 warps (2x4), double-buffered smem
__global__ __launch_bounds__(256) void k_gemm_out(const float* __restrict__ b_out,
                                                  float* __restrict__ out) {
    const int K = Hsz;
    __shared__ __nv_bfloat16 As[2][128 * 40];
    __shared__ __nv_bfloat16 Bs[2][128 * 40];
    int m0 = blockIdx.y * 128, n0 = blockIdx.x * 128;
    int tid = threadIdx.x;
    int warp = tid >> 5, lane = tid & 31;
    int wm = warp >> 2, wn = warp & 3;
    int lrow = tid >> 2;
    int kch = (tid & 3) * 8;

    wmma::fragment<wmma::accumulator, 16, 16, 16, float> acc[4][2];
#pragma unroll
    for (int i = 0; i < 4; i++)
#pragma unroll
        for (int j = 0; j < 2; j++) wmma::fill_fragment(acc[i][j], 0.f);

    const __nv_bfloat16* Ag = g_hall + (size_t)(m0 + lrow) * K + kch;
    const __nv_bfloat16* Bg = g_wout + (size_t)(n0 + lrow) * K + kch;

    uint4 ra0, ra1, rb0, rb1;
    ra0 = *(const uint4*)(Ag);            ra1 = *(const uint4*)(Ag + 64 * K);
    rb0 = *(const uint4*)(Bg);            rb1 = *(const uint4*)(Bg + 64 * K);
    *(uint4*)&As[0][lrow * 40 + kch] = ra0;
    *(uint4*)&As[0][(lrow + 64) * 40 + kch] = ra1;
    *(uint4*)&Bs[0][lrow * 40 + kch] = rb0;
    *(uint4*)&Bs[0][(lrow + 64) * 40 + kch] = rb1;
    __syncthreads();

    const int NKT = K / 32;
    for (int kt = 0; kt < NKT; kt++) {
        int cur = kt & 1, nxt = cur ^ 1;
        if (kt + 1 < NKT) {
            const __nv_bfloat16* a = Ag + (kt + 1) * 32;
            ra0 = *(const uint4*)(a);     ra1 = *(const uint4*)(a + 64 * K);
            const __nv_bfloat16* bp = Bg + (kt + 1) * 32;
            rb0 = *(const uint4*)(bp);    rb1 = *(const uint4*)(bp + 64 * K);
        }
#pragma unroll
        for (int ks = 0; ks < 2; ks++) {
            wmma::fragment<wmma::matrix_a, 16, 16, 16, __nv_bfloat16, wmma::row_major> af[4];
            wmma::fragment<wmma::matrix_b, 16, 16, 16, __nv_bfloat16, wmma::col_major> bf[2];
#pragma unroll
            for (int i = 0; i < 4; i++)
                wmma::load_matrix_sync(af[i], &As[cur][(wm * 64 + i * 16) * 40 + ks * 16], 40);
#pragma unroll
            for (int j = 0; j < 2; j++)
                wmma::load_matrix_sync(bf[j], &Bs[cur][(wn * 32 + j * 16) * 40 + ks * 16], 40);
#pragma unroll
            for (int i = 0; i < 4; i++)
#pragma unroll
                for (int j = 0; j < 2; j++)
                    wmma::mma_sync(acc[i][j], af[i], bf[j], acc[i][j]);
        }
        if (kt + 1 < NKT) {
            *(uint4*)&As[nxt][lrow * 40 + kch] = ra0;
            *(uint4*)&As[nxt][(lrow + 64) * 40 + kch] = ra1;
            *(uint4*)&Bs[nxt][lrow * 40 + kch] = rb0;
            *(uint4*)&Bs[nxt][(lrow + 64) * 40 + kch] = rb1;
        }
        __syncthreads();
    }

    // epilogue: stage per-warp 16x16 tiles, remap rows (t*64+b) -> out[(b*T+t)*V]
    float* stage = (float*)&As[0][0];
    float* sp = stage + warp * 320;  // 16 * 20 per warp
#pragma unroll
    for (int i = 0; i < 4; i++) {
#pragma unroll
        for (int j = 0; j < 2; j++) {
            wmma::store_matrix_sync(sp, acc[i][j], 20, wmma::mem_row_major);
            __syncwarp();
            int gr0 = m0 + wm * 64 + i * 16;
            int gc0 = n0 + wn * 32 + j * 16;
            for (int e = lane; e < 256; e += 32) {
                int r = e >> 4, cc = e & 15;
                int gr = gr0 + r, gc = gc0 + cc;
                int bb = gr & 63, tt = gr >> 6;
                out[(size_t)(bb * Tsz + tt) * Vsz + gc] = sp[r * 20 + cc] + b_out[gc];
            }
            __syncwarp();
        }
    }
}

// ---------------- in-place log_softmax over V per (b,t) row ----------------
__global__ __launch_bounds__(256) void k_logsoftmax(float* __restrict__ out) {
    int row = blockIdx.x;
    float* p = out + (size_t)row * Vsz;
    int tid = threadIdx.x;
    float m = -1e30f, s = 0.f;
    for (int j = tid; j < Vsz; j += 256) {
        float v = p[j];
        if (v > m) { s = s * __expf(m - v) + 1.f; m = v; }
        else       { s += __expf(v - m); }
    }
    __shared__ float sm[256], ss[256];
    sm[tid] = m; ss[tid] = s;
    __syncthreads();
    for (int o = 128; o > 0; o >>= 1) {
        if (tid < o) {
            float m2 = sm[tid + o], s2 = ss[tid + o];
            float mm = fmaxf(sm[tid], m2);
            ss[tid] = ss[tid] * __expf(sm[tid] - mm) + s2 * __expf(m2 - mm);
            sm[tid] = mm;
        }
        __syncthreads();
    }
    float L = sm[0] + logf(ss[0]);
    for (int j = tid; j < Vsz; j += 256) p[j] = p[j] - L;
}

__global__ void k_hidden(float* __restrict__ out) {
    int i = blockIdx.x * blockDim.x + threadIdx.x;
    if (i < Bsz * Hsz) out[i] = g_h[i];
}

// ---------------- launch ----------------
extern "C" void kernel_launch(void* const* d_in, const int* in_sizes, int n_in,
                              void* d_out, int out_size) {
    const float* enc_out = (const float*)d_in[0];
    const float* enc_hid = (const float*)d_in[1];
    const int*   target  = (const int*)d_in[2];
    const float* embedding = (const float*)d_in[3];
    const float* Wa  = (const float*)d_in[4];
    const float* ba  = (const float*)d_in[5];
    const float* Ua  = (const float*)d_in[6];
    const float* bu  = (const float*)d_in[7];
    const float* Va  = (const float*)d_in[8];
    // d_in[9] = bv : softmax shift-invariant, unused
    const float* W_ih = (const float*)d_in[10];
    const float* W_hh = (const float*)d_in[11];
    const float* b_ih = (const float*)d_in[12];
    const float* b_hh = (const float*)d_in[13];
    const float* W_out = (const float*)d_in[14];
    const float* b_out = (const float*)d_in[15];

    float* out = (float*)d_out;
    float* out_dec  = out;                                        // [B,T,V]
    float* out_hid  = out + (size_t)Bsz * Tsz * Vsz;              // [1,B,H]
    float* out_attn = out_hid + (size_t)Bsz * Hsz;                // [B,T,S]

    // --- init (once per replay) ---
    k_init_h<<<(Bsz * Hsz + 255) / 256, 256>>>(enc_hid);
    k_embed<<<Tsz * Bsz, 256>>>(target, embedding);
    {
        float* keysU = nullptr;  cudaGetSymbolAddress((void**)&keysU, g_keysU);
        dim3 grid(Hsz / 64, (Bsz * Ssz) / 64);
        k_gemm_keysu<<<grid, 256>>>(enc_out, Ua, keysU);
    }
    k_keysu_bias<<<4096, 256>>>(ba, bu);
    k_wout_conv<<<2048, 256>>>(W_out);

    // --- recurrence ---
    for (int t = 0; t < Tsz; t++) {
        k_gemm_q<<<Hsz / 64, 256>>>(Wa);
        k_attn<<<Bsz, 256>>>(t, enc_out, Va, out_attn);
        k_gemm_gru<<<96, 256>>>(W_ih, W_hh);
        k_gates<<<Bsz, 256>>>(t, b_ih, b_hh);
    }

    // --- batched output projection + log_softmax + hidden ---
    {
        dim3 grid(Vsz / 128, (Tsz * Bsz) / 128);  // 250 x 20
        k_gemm_out<<<grid, 256>>>(b_out, out_dec);
    }
    k_logsoftmax<<<Tsz * Bsz, 256>>>(out_dec);
    k_hidden<<<(Bsz * Hsz + 255) / 256, 256>>>(out_hid);
}

// round 4
// speedup vs baseline: 4.2372x; 1.3533x over previous
#include <cuda_runtime.h>
#include <cuda_bf16.h>
#include <mma.h>

using namespace nvcuda;

#define Bsz 64
#define Ssz 64
#define Hsz 1024
#define Vsz 32000
#define Tsz 40
#define NBLK 148
#define NTHR 256

// ---------------- scratch ----------------
__device__ float g_keysU[Bsz * Ssz * Hsz];          // 16 MB, includes ba+bu bias
__device__ float g_emb[Tsz * Bsz * Hsz];            // 10 MB  [t][b][h]
__device__ float g_h[Bsz * Hsz];
__device__ float g_q[Bsz * Hsz];
__device__ float g_ctx[Bsz * Hsz];
__device__ float g_sc[Bsz * Ssz];
__device__ float g_gh[Bsz * 3 * Hsz];
__device__ float g_giA[Bsz * 3 * Hsz];
__device__ float g_giB[Bsz * 3 * Hsz];
__device__ __nv_bfloat16 g_hall[Tsz * Bsz * Hsz];   // 5 MB
__device__ __nv_bfloat16 g_wout[Vsz * Hsz];         // 65 MB
__device__ unsigned g_barcnt = 0;
__device__ unsigned g_bargen = 0;

// fast activations
__device__ __forceinline__ float tanh_fast(float x) {   // MUFU.TANH, scores only
    float y; asm("tanh.approx.f32 %0, %1;" : "=f"(y) : "f"(x)); return y;
}
__device__ __forceinline__ float ftanh(float x) {       // accurate-ish, gates
    float e = __expf(2.f * x);
    return 1.f - __fdividef(2.f, e + 1.f);
}
__device__ __forceinline__ float fsigmoid(float x) {
    return __fdividef(1.f, 1.f + __expf(-x));
}

// ---------------- init kernels ----------------
__global__ void k_embed(const int* __restrict__ target, const float* __restrict__ emb) {
    int t = blockIdx.x / Bsz, b = blockIdx.x % Bsz;
    int tok = (t == 0) ? 0 : target[b * Tsz + t - 1];
    const float4* src = (const float4*)(emb + (size_t)tok * Hsz);
    float4* dst = (float4*)(g_emb + ((size_t)t * Bsz + b) * Hsz);
    for (int j = threadIdx.x; j < Hsz / 4; j += blockDim.x) dst[j] = src[j];
}

__global__ void k_init_h(const float* __restrict__ eh) {
    int i = blockIdx.x * blockDim.x + threadIdx.x;
    if (i < Bsz * Hsz) g_h[i] = eh[i];
}

__global__ void k_wout_conv(const float* __restrict__ W) {
    int n4 = Vsz * Hsz / 4;
    for (int i = blockIdx.x * blockDim.x + threadIdx.x; i < n4; i += gridDim.x * blockDim.x) {
        float4 v = ((const float4*)W)[i];
        ((__nv_bfloat162*)g_wout)[2 * i]     = __floats2bfloat162_rn(v.x, v.y);
        ((__nv_bfloat162*)g_wout)[2 * i + 1] = __floats2bfloat162_rn(v.z, v.w);
    }
}

__global__ void k_keysu_bias(const float* __restrict__ ba, const float* __restrict__ bu) {
    int total = Bsz * Ssz * Hsz;
    for (int i = blockIdx.x * blockDim.x + threadIdx.x; i < total; i += gridDim.x * blockDim.x) {
        int n = i & (Hsz - 1);
        g_keysU[i] += ba[n] + bu[n];
    }
}

// ---------------- 64x64x1024 tf32 tile GEMM, BK=16 double-buffered ----------------
// A: 64 rows (tile-origin), lda; B: 64 rows (tile-origin, row n = output col), ldb;
// C: tile origin, ldc. 256 threads.
__device__ __forceinline__ void gemm64(const float* __restrict__ A, int lda,
                                       const float* __restrict__ B, int ldb,
                                       float* __restrict__ C, int ldc,
                                       float* sAB) {
    float (*As)[64][20] = (float(*)[64][20])sAB;
    float (*Bs)[64][20] = (float(*)[64][20])(sAB + 2560);
    int tid = threadIdx.x;
    int r = tid >> 2;
    int c = (tid & 3) * 4;
    int warp = tid >> 5, wm = warp >> 1, wn = warp & 1;

    wmma::fragment<wmma::accumulator, 16, 16, 8, float> acc[2];
    wmma::fill_fragment(acc[0], 0.f);
    wmma::fill_fragment(acc[1], 0.f);

    const float* Ap = A + (size_t)r * lda + c;
    const float* Bp = B + (size_t)r * ldb + c;
    float4 a = *(const float4*)Ap;
    float4 b = *(const float4*)Bp;
    *(float4*)&As[0][r][c] = a;
    *(float4*)&Bs[0][r][c] = b;
    __syncthreads();

    for (int it = 0; it < 64; it++) {
        int cur = it & 1, nxt = cur ^ 1;
        if (it < 63) {
            a = *(const float4*)(Ap + (it + 1) * 16);
            b = *(const float4*)(Bp + (it + 1) * 16);
        }
#pragma unroll
        for (int ks = 0; ks < 2; ks++) {
            wmma::fragment<wmma::matrix_a, 16, 16, 8, wmma::precision::tf32, wmma::row_major> af;
            wmma::load_matrix_sync(af, &As[cur][wm * 16][ks * 8], 20);
#pragma unroll
            for (int e = 0; e < af.num_elements; e++) af.x[e] = wmma::__float_to_tf32(af.x[e]);
#pragma unroll
            for (int j = 0; j < 2; j++) {
                wmma::fragment<wmma::matrix_b, 16, 16, 8, wmma::precision::tf32, wmma::col_major> bf;
                wmma::load_matrix_sync(bf, &Bs[cur][wn * 32 + j * 16][ks * 8], 20);
#pragma unroll
                for (int e = 0; e < bf.num_elements; e++) bf.x[e] = wmma::__float_to_tf32(bf.x[e]);
                wmma::mma_sync(acc[j], af, bf, acc[j]);
            }
        }
        if (it < 63) {
            *(float4*)&As[nxt][r][c] = a;
            *(float4*)&Bs[nxt][r][c] = b;
        }
        __syncthreads();
    }
    wmma::store_matrix_sync(C + (size_t)(wm * 16) * ldc + wn * 32, acc[0], ldc, wmma::mem_row_major);
    wmma::store_matrix_sync(C + (size_t)(wm * 16) * ldc + wn * 32 + 16, acc[1], ldc, wmma::mem_row_major);
}

// keysU = enc @ Ua^T  (grid 16 x 64)
__global__ __launch_bounds__(NTHR) void k_gemm_keysu(const float* __restrict__ enc,
                                                     const float* __restrict__ Ua) {
    __shared__ float sAB[5120];
    int m0 = blockIdx.y * 64, n0 = blockIdx.x * 64;
    gemm64(enc + (size_t)m0 * Hsz, Hsz, Ua + (size_t)n0 * Hsz, Hsz,
           g_keysU + (size_t)m0 * Hsz + n0, Hsz, sAB);
}

// ---------------- the persistent recurrence kernel ----------------
__global__ __launch_bounds__(NTHR, 1) void k_persist(
    const float* __restrict__ enc, const float* __restrict__ Wa,
    const float* __restrict__ Va,
    const float* __restrict__ W_ih, const float* __restrict__ W_hh,
    const float* __restrict__ b_ih, const float* __restrict__ b_hh,
    float* __restrict__ out_attn, float* __restrict__ out_hid)
{
    __shared__ float sAB[5120];
    __shared__ unsigned s_gen0;
    int tid = threadIdx.x;
    int bx = blockIdx.x;
    if (tid == 0) s_gen0 = *((volatile unsigned*)&g_bargen);
    __syncthreads();
    unsigned gen = s_gen0;

    auto gbar = [&]() {
        gen++;
        __syncthreads();
        if (tid == 0) {
            __threadfence();
            unsigned a = atomicAdd(&g_barcnt, 1u);
            if (a == NBLK - 1) {
                g_barcnt = 0;
                __threadfence();
                *((volatile unsigned*)&g_bargen) = gen;
            } else {
                while (*((volatile unsigned*)&g_bargen) != gen) __nanosleep(32);
                __threadfence();
            }
        }
        __syncthreads();
    };

    for (int t = 0; t < Tsz; t++) {
        // ---- Phase A: q = h@Wa^T (16 tiles) | gh = h@W_hh^T (48 tiles) ----
        if (bx < 64) {
            if (bx < 16) {
                int n0 = bx * 64;
                gemm64(g_h, Hsz, Wa + (size_t)n0 * Hsz, Hsz, g_q + n0, Hsz, sAB);
            } else {
                int jt = bx - 16, n0 = jt * 64;
                gemm64(g_h, Hsz, W_hh + (size_t)n0 * Hsz, Hsz, g_gh + n0, 3 * Hsz, sAB);
            }
        }
        gbar();

        // ---- Phase B: scores[b,s] = Va . tanh(q[b] + keysU[b,s]) ----
        {
            int gw = bx * 8 + (tid >> 5);
            int lane = tid & 31;
            for (int p = gw; p < Bsz * Ssz; p += NBLK * 8) {
                int b = p >> 6;
                const float* kp = g_keysU + (size_t)p * Hsz;
                const float* qp = g_q + b * Hsz;
                float acc = 0.f;
#pragma unroll 8
                for (int jj = 0; jj < 32; jj++) {
                    int j = lane + jj * 32;
                    acc += Va[j] * tanh_fast(qp[j] + kp[j]);
                }
#pragma unroll
                for (int o = 16; o > 0; o >>= 1) acc += __shfl_xor_sync(0xffffffffu, acc, o);
                if (lane == 0) g_sc[p] = acc;
            }
        }
        gbar();

        // ---- Phase C: softmax + ctx (64 blocks) ----
        if (bx < 64) {
            int b = bx;
            float* ws = sAB;  // reuse smem
            int warp = tid >> 5, lane = tid & 31;
            if (warp == 0) {
                float v0 = g_sc[b * 64 + lane], v1 = g_sc[b * 64 + 32 + lane];
                float m = fmaxf(v0, v1);
#pragma unroll
                for (int o = 16; o > 0; o >>= 1) m = fmaxf(m, __shfl_xor_sync(0xffffffffu, m, o));
                float e0 = __expf(v0 - m), e1 = __expf(v1 - m);
                float ssum = e0 + e1;
#pragma unroll
                for (int o = 16; o > 0; o >>= 1) ssum += __shfl_xor_sync(0xffffffffu, ssum, o);
                float inv = __fdividef(1.f, ssum);
                ws[lane] = e0 * inv;
                ws[lane + 32] = e1 * inv;
            }
            __syncthreads();
            if (tid < Ssz) out_attn[(size_t)b * Tsz * Ssz + t * Ssz + tid] = ws[tid];
            float c0 = 0.f, c1 = 0.f, c2 = 0.f, c3 = 0.f;
            const float* ep = enc + (size_t)b * Ssz * Hsz + tid;
#pragma unroll 4
            for (int s = 0; s < Ssz; s++) {
                float w = ws[s];
                const float* row = ep + (size_t)s * Hsz;
                c0 += w * row[0];
                c1 += w * row[256];
                c2 += w * row[512];
                c3 += w * row[768];
            }
            g_ctx[b * Hsz + tid]       = c0;
            g_ctx[b * Hsz + tid + 256] = c1;
            g_ctx[b * Hsz + tid + 512] = c2;
            g_ctx[b * Hsz + tid + 768] = c3;
        }
        gbar();

        // ---- Phase D: gi = emb_t@Wl^T + ctx@Wr^T  (96 half-K tiles) ----
        if (bx < 96) {
            int jt = bx >> 1, kh = bx & 1, n0 = jt * 64;
            const float* A = kh ? g_ctx : (g_emb + (size_t)t * Bsz * Hsz);
            const float* Bm = W_ih + (size_t)n0 * (2 * Hsz) + kh * Hsz;
            float* C = (kh ? g_giB : g_giA) + n0;
            gemm64(A, Hsz, Bm, 2 * Hsz, C, 3 * Hsz, sAB);
        }
        gbar();

        // ---- Phase E: gates + h update (all blocks) ----
        for (int i = bx * NTHR + tid; i < Bsz * Hsz; i += NBLK * NTHR) {
            int b = i >> 10, j = i & (Hsz - 1);
            const float* giA = g_giA + (size_t)b * 3 * Hsz;
            const float* giB = g_giB + (size_t)b * 3 * Hsz;
            const float* gh  = g_gh  + (size_t)b * 3 * Hsz;
            float ir = giA[j]            + giB[j]            + b_ih[j];
            float iz = giA[Hsz + j]      + giB[Hsz + j]      + b_ih[Hsz + j];
            float in = giA[2 * Hsz + j]  + giB[2 * Hsz + j]  + b_ih[2 * Hsz + j];
            float hr = gh[j]             + b_hh[j];
            float hz = gh[Hsz + j]       + b_hh[Hsz + j];
            float hn = gh[2 * Hsz + j]   + b_hh[2 * Hsz + j];
            float rr = fsigmoid(ir + hr);
            float zz = fsigmoid(iz + hz);
            float nn = ftanh(in + rr * hn);
            float hp = g_h[i];
            float hnew = (1.f - zz) * nn + zz * hp;
            g_h[i] = hnew;
            g_hall[((size_t)t * Bsz + b) * Hsz + j] = __float2bfloat16(hnew);
        }
        gbar();
    }

    // final hidden copy
    for (int i = bx * NTHR + tid; i < Bsz * Hsz; i += NBLK * NTHR)
        out_hid[i] = g_h[i];
}

// ---------------- batched output projection: logits = Hall @ Wout^T + b_out ----------------
__global__ __launch_bounds__(256) void k_gemm_out(const float* __restrict__ b_out,
                                                  float* __restrict__ out) {
    const int K = Hsz;
    __shared__ __nv_bfloat16 As[2][128 * 40];
    __shared__ __nv_bfloat16 Bs[2][128 * 40];
    int m0 = blockIdx.y * 128, n0 = blockIdx.x * 128;
    int tid = threadIdx.x;
    int warp = tid >> 5, lane = tid & 31;
    int wm = warp >> 2, wn = warp & 3;
    int lrow = tid >> 2;
    int kch = (tid & 3) * 8;

    wmma::fragment<wmma::accumulator, 16, 16, 16, float> acc[4][2];
#pragma unroll
    for (int i = 0; i < 4; i++)
#pragma unroll
        for (int j = 0; j < 2; j++) wmma::fill_fragment(acc[i][j], 0.f);

    const __nv_bfloat16* Ag = g_hall + (size_t)(m0 + lrow) * K + kch;
    const __nv_bfloat16* Bg = g_wout + (size_t)(n0 + lrow) * K + kch;

    uint4 ra0, ra1, rb0, rb1;
    ra0 = *(const uint4*)(Ag);            ra1 = *(const uint4*)(Ag + 64 * K);
    rb0 = *(const uint4*)(Bg);            rb1 = *(const uint4*)(Bg + 64 * K);
    *(uint4*)&As[0][lrow * 40 + kch] = ra0;
    *(uint4*)&As[0][(lrow + 64) * 40 + kch] = ra1;
    *(uint4*)&Bs[0][lrow * 40 + kch] = rb0;
    *(uint4*)&Bs[0][(lrow + 64) * 40 + kch] = rb1;
    __syncthreads();

    const int NKT = K / 32;
    for (int kt = 0; kt < NKT; kt++) {
        int cur = kt & 1, nxt = cur ^ 1;
        if (kt + 1 < NKT) {
            const __nv_bfloat16* a = Ag + (kt + 1) * 32;
            ra0 = *(const uint4*)(a);     ra1 = *(const uint4*)(a + 64 * K);
            const __nv_bfloat16* bp = Bg + (kt + 1) * 32;
            rb0 = *(const uint4*)(bp);    rb1 = *(const uint4*)(bp + 64 * K);
        }
#pragma unroll
        for (int ks = 0; ks < 2; ks++) {
            wmma::fragment<wmma::matrix_a, 16, 16, 16, __nv_bfloat16, wmma::row_major> af[4];
            wmma::fragment<wmma::matrix_b, 16, 16, 16, __nv_bfloat16, wmma::col_major> bf[2];
#pragma unroll
            for (int i = 0; i < 4; i++)
                wmma::load_matrix_sync(af[i], &As[cur][(wm * 64 + i * 16) * 40 + ks * 16], 40);
#pragma unroll
            for (int j = 0; j < 2; j++)
                wmma::load_matrix_sync(bf[j], &Bs[cur][(wn * 32 + j * 16) * 40 + ks * 16], 40);
#pragma unroll
            for (int i = 0; i < 4; i++)
#pragma unroll
                for (int j = 0; j < 2; j++)
                    wmma::mma_sync(acc[i][j], af[i], bf[j], acc[i][j]);
        }
        if (kt + 1 < NKT) {
            *(uint4*)&As[nxt][lrow * 40 + kch] = ra0;
            *(uint4*)&As[nxt][(lrow + 64) * 40 + kch] = ra1;
            *(uint4*)&Bs[nxt][lrow * 40 + kch] = rb0;
            *(uint4*)&Bs[nxt][(lrow + 64) * 40 + kch] = rb1;
        }
        __syncthreads();
    }

    float* stage = (float*)&As[0][0];
    float* sp = stage + warp * 320;
#pragma unroll
    for (int i = 0; i < 4; i++) {
#pragma unroll
        for (int j = 0; j < 2; j++) {
            wmma::store_matrix_sync(sp, acc[i][j], 20, wmma::mem_row_major);
            __syncwarp();
            int gr0 = m0 + wm * 64 + i * 16;
            int gc0 = n0 + wn * 32 + j * 16;
            for (int e = lane; e < 256; e += 32) {
                int r = e >> 4, cc = e & 15;
                int gr = gr0 + r, gc = gc0 + cc;
                int bb = gr & 63, tt = gr >> 6;
                out[(size_t)(bb * Tsz + tt) * Vsz + gc] = sp[r * 20 + cc] + b_out[gc];
            }
            __syncwarp();
        }
    }
}

// ---------------- in-place log_softmax ----------------
__global__ __launch_bounds__(256) void k_logsoftmax(float* __restrict__ out) {
    int row = blockIdx.x;
    float* p = out + (size_t)row * Vsz;
    int tid = threadIdx.x;
    float m = -1e30f, s = 0.f;
    for (int j = tid; j < Vsz; j += 256) {
        float v = p[j];
        if (v > m) { s = s * __expf(m - v) + 1.f; m = v; }
        else       { s += __expf(v - m); }
    }
    __shared__ float sm[256], ss[256];
    sm[tid] = m; ss[tid] = s;
    __syncthreads();
    for (int o = 128; o > 0; o >>= 1) {
        if (tid < o) {
            float m2 = sm[tid + o], s2 = ss[tid + o];
            float mm = fmaxf(sm[tid], m2);
            ss[tid] = ss[tid] * __expf(sm[tid] - mm) + s2 * __expf(m2 - mm);
            sm[tid] = mm;
        }
        __syncthreads();
    }
    float L = sm[0] + logf(ss[0]);
    for (int j = tid; j < Vsz; j += 256) p[j] = p[j] - L;
}

// ---------------- launch ----------------
extern "C" void kernel_launch(void* const* d_in, const int* in_sizes, int n_in,
                              void* d_out, int out_size) {
    const float* enc_out = (const float*)d_in[0];
    const float* enc_hid = (const float*)d_in[1];
    const int*   target  = (const int*)d_in[2];
    const float* embedding = (const float*)d_in[3];
    const float* Wa  = (const float*)d_in[4];
    const float* ba  = (const float*)d_in[5];
    const float* Ua  = (const float*)d_in[6];
    const float* bu  = (const float*)d_in[7];
    const float* Va  = (const float*)d_in[8];
    // d_in[9] = bv : softmax shift-invariant, unused
    const float* W_ih = (const float*)d_in[10];
    const float* W_hh = (const float*)d_in[11];
    const float* b_ih = (const float*)d_in[12];
    const float* b_hh = (const float*)d_in[13];
    const float* W_out = (const float*)d_in[14];
    const float* b_out = (const float*)d_in[15];

    float* out = (float*)d_out;
    float* out_dec  = out;                                        // [B,T,V]
    float* out_hid  = out + (size_t)Bsz * Tsz * Vsz;              // [1,B,H]
    float* out_attn = out_hid + (size_t)Bsz * Hsz;                // [B,T,S]

    // init
    k_embed<<<Tsz * Bsz, 256>>>(target, embedding);
    k_init_h<<<(Bsz * Hsz + 255) / 256, 256>>>(enc_hid);
    k_wout_conv<<<2048, 256>>>(W_out);
    {
        dim3 grid(Hsz / 64, (Bsz * Ssz) / 64);
        k_gemm_keysu<<<grid, NTHR>>>(enc_out, Ua);
    }
    k_keysu_bias<<<4096, 256>>>(ba, bu);

    // full recurrence in one launch
    k_persist<<<NBLK, NTHR>>>(enc_out, Wa, Va, W_ih, W_hh, b_ih, b_hh,
                              out_attn, out_hid);

    // output projection + log_softmax
    {
        dim3 grid(Vsz / 128, (Tsz * Bsz) / 128);
        k_gemm_out<<<grid, 256>>>(b_out, out_dec);
    }
    k_logsoftmax<<<Tsz * Bsz, 256>>>(out_dec);
}

// round 5
// speedup vs baseline: 7.4446x; 1.7570x over previous
#include <cuda_runtime.h>
#include <cuda_bf16.h>
#include <mma.h>

using namespace nvcuda;

#define Bsz 64
#define Ssz 64
#define Hsz 1024
#define Vsz 32000
#define Tsz 40
#define NBLK 148
#define NTHR 256

// ---------------- scratch ----------------
__device__ float g_keysU[Bsz * Ssz * Hsz];          // 16 MB (includes ba+bu)
__device__ float g_emb[Tsz * Bsz * Hsz];            // 10 MB [t][b][h]
__device__ float g_h[Bsz * Hsz];
__device__ float g_q2[2][Bsz * Hsz];                // q split-K parts
__device__ float g_gh2[2][Bsz * 3 * Hsz];           // gh split-K parts
__device__ float g_gc2[2][Bsz * 3 * Hsz];           // gi ctx-half split-K parts
__device__ float g_giE[(size_t)Tsz * Bsz * 3 * Hsz];// 31.5 MB precomputed emb-half of gi
__device__ float g_ctx[Bsz * Hsz];
__device__ __nv_bfloat16 g_hall[Tsz * Bsz * Hsz];   // 5 MB
__device__ __nv_bfloat16 g_wout[Vsz * Hsz];         // 65 MB
__device__ unsigned g_barcnt = 0;
__device__ unsigned g_bargen = 0;

// fast activations
__device__ __forceinline__ float tanh_fast(float x) {
    float y; asm("tanh.approx.f32 %0, %1;" : "=f"(y) : "f"(x)); return y;
}
__device__ __forceinline__ float ftanh(float x) {
    float e = __expf(2.f * x);
    return 1.f - __fdividef(2.f, e + 1.f);
}
__device__ __forceinline__ float fsigmoid(float x) {
    return __fdividef(1.f, 1.f + __expf(-x));
}

// cp.async helpers
__device__ __forceinline__ void cp16(void* sdst, const void* gsrc) {
    unsigned s = (unsigned)__cvta_generic_to_shared(sdst);
    asm volatile("cp.async.cg.shared.global [%0], [%1], 16;\n" :: "r"(s), "l"(gsrc));
}
#define CP_COMMIT() asm volatile("cp.async.commit_group;\n")
#define CP_WAIT1()  asm volatile("cp.async.wait_group 1;\n")

// ---------------- init kernels ----------------
__global__ void k_embed(const int* __restrict__ target, const float* __restrict__ emb) {
    int t = blockIdx.x / Bsz, b = blockIdx.x % Bsz;
    int tok = (t == 0) ? 0 : target[b * Tsz + t - 1];
    const float4* src = (const float4*)(emb + (size_t)tok * Hsz);
    float4* dst = (float4*)(g_emb + ((size_t)t * Bsz + b) * Hsz);
    for (int j = threadIdx.x; j < Hsz / 4; j += blockDim.x) dst[j] = src[j];
}

__global__ void k_init_h(const float* __restrict__ eh) {
    int i = blockIdx.x * blockDim.x + threadIdx.x;
    if (i < Bsz * Hsz) g_h[i] = eh[i];
}

__global__ void k_wout_conv(const float* __restrict__ W) {
    int n4 = Vsz * Hsz / 4;
    for (int i = blockIdx.x * blockDim.x + threadIdx.x; i < n4; i += gridDim.x * blockDim.x) {
        float4 v = ((const float4*)W)[i];
        ((__nv_bfloat162*)g_wout)[2 * i]     = __floats2bfloat162_rn(v.x, v.y);
        ((__nv_bfloat162*)g_wout)[2 * i + 1] = __floats2bfloat162_rn(v.z, v.w);
    }
}

__global__ void k_keysu_bias(const float* __restrict__ ba, const float* __restrict__ bu) {
    int total = Bsz * Ssz * Hsz;
    for (int i = blockIdx.x * blockDim.x + threadIdx.x; i < total; i += gridDim.x * blockDim.x) {
        int n = i & (Hsz - 1);
        g_keysU[i] += ba[n] + bu[n];
    }
}

// ---------------- tf32 64x64 tile GEMM, cp.async 3-stage, BK=16 ----------------
// C[0:64, n-tile] = A[0:64, 0:16*kiters] @ B[rows=out cols][same K]^T
// smem: float buf[3*64*20 * 2] = 30720 B.  256 threads.
__device__ __forceinline__ void gemm64cp(const float* __restrict__ A, int lda,
                                         const float* __restrict__ B, int ldb,
                                         float* __restrict__ C, int ldc,
                                         int kiters, float* sbuf) {
    float (*As)[64][20] = (float(*)[64][20])sbuf;
    float (*Bs)[64][20] = (float(*)[64][20])(sbuf + 3 * 64 * 20);
    int tid = threadIdx.x;
    int r = tid >> 2;
    int c4 = (tid & 3) << 2;
    int warp = tid >> 5, wm = warp >> 1, wn = warp & 1;

    const float* Ap = A + (size_t)r * lda + c4;
    const float* Bp = B + (size_t)r * ldb + c4;

    wmma::fragment<wmma::accumulator, 16, 16, 8, float> acc0, acc1;
    wmma::fill_fragment(acc0, 0.f);
    wmma::fill_fragment(acc1, 0.f);

    // prologue: stages 0,1
#pragma unroll
    for (int s = 0; s < 2; s++) {
        if (s < kiters) {
            cp16(&As[s][r][c4], Ap + s * 16);
            cp16(&Bs[s][r][c4], Bp + s * 16);
        }
        CP_COMMIT();
    }

    int stg = 2;
    for (int it = 0; it < kiters; it++) {
        int cur = it % 3;
        CP_WAIT1();
        __syncthreads();
        if (it + 2 < kiters) {
            cp16(&As[stg][r][c4], Ap + (it + 2) * 16);
            cp16(&Bs[stg][r][c4], Bp + (it + 2) * 16);
        }
        CP_COMMIT();
        stg++; if (stg == 3) stg = 0;
#pragma unroll
        for (int ks = 0; ks < 2; ks++) {
            wmma::fragment<wmma::matrix_a, 16, 16, 8, wmma::precision::tf32, wmma::row_major> af;
            wmma::fragment<wmma::matrix_b, 16, 16, 8, wmma::precision::tf32, wmma::col_major> bf0, bf1;
            wmma::load_matrix_sync(af, &As[cur][wm * 16][ks * 8], 20);
            wmma::load_matrix_sync(bf0, &Bs[cur][wn * 32][ks * 8], 20);
            wmma::load_matrix_sync(bf1, &Bs[cur][wn * 32 + 16][ks * 8], 20);
            wmma::mma_sync(acc0, af, bf0, acc0);
            wmma::mma_sync(acc1, af, bf1, acc1);
        }
    }
    __syncthreads();
    wmma::store_matrix_sync(C + (size_t)(wm * 16) * ldc + wn * 32, acc0, ldc, wmma::mem_row_major);
    wmma::store_matrix_sync(C + (size_t)(wm * 16) * ldc + wn * 32 + 16, acc1, ldc, wmma::mem_row_major);
}

// keysU = enc @ Ua^T  (grid 16 x 64)
__global__ __launch_bounds__(NTHR, 2) void k_gemm_keysu(const float* __restrict__ enc,
                                                        const float* __restrict__ Ua) {
    __shared__ float sbuf[7680];
    int m0 = blockIdx.y * 64, n0 = blockIdx.x * 64;
    gemm64cp(enc + (size_t)m0 * Hsz, Hsz, Ua + (size_t)n0 * Hsz, Hsz,
             g_keysU + (size_t)m0 * Hsz + n0, Hsz, 64, sbuf);
}

// gi_emb[t] = emb_t @ W_ih[:, 0:H]^T  (grid 48 x 40)
__global__ __launch_bounds__(NTHR, 2) void k_gemm_giemb(const float* __restrict__ W_ih) {
    __shared__ float sbuf[7680];
    int n0 = blockIdx.x * 64;
    int t = blockIdx.y;
    gemm64cp(g_emb + (size_t)t * Bsz * Hsz, Hsz,
             W_ih + (size_t)n0 * (2 * Hsz), 2 * Hsz,
             g_giE + (size_t)t * Bsz * 3 * Hsz + n0, 3 * Hsz, 64, sbuf);
}

// ---------------- persistent recurrence kernel ----------------
__global__ __launch_bounds__(NTHR, 1) void k_persist(
    const float* __restrict__ enc, const float* __restrict__ Wa,
    const float* __restrict__ Va,
    const float* __restrict__ W_ih, const float* __restrict__ W_hh,
    const float* __restrict__ b_ih, const float* __restrict__ b_hh,
    float* __restrict__ out_attn, float* __restrict__ out_hid)
{
    __shared__ float sbuf[7680];
    __shared__ unsigned s_gen0;
    int tid = threadIdx.x;
    int bx = blockIdx.x;
    if (tid == 0) s_gen0 = *((volatile unsigned*)&g_bargen);
    __syncthreads();
    unsigned gen = s_gen0;

    auto gbar = [&]() {
        gen++;
        __syncthreads();
        if (tid == 0) {
            __threadfence();
            unsigned a = atomicAdd(&g_barcnt, 1u);
            if (a == NBLK - 1) {
                g_barcnt = 0;
                __threadfence();
                *((volatile unsigned*)&g_bargen) = gen;
            } else {
                while (*((volatile unsigned*)&g_bargen) != gen) __nanosleep(32);
                __threadfence();
            }
        }
        __syncthreads();
    };

    for (int t = 0; t < Tsz; t++) {
        // ---- Phase A: q = h@Wa^T (32 part-tiles) | gh = h@W_hh^T (96 part-tiles), K=512 each
        if (bx < 128) {
            if (bx < 32) {
                int jt = bx >> 1, kh = bx & 1, n0 = jt * 64;
                gemm64cp(g_h + kh * 512, Hsz,
                         Wa + (size_t)n0 * Hsz + kh * 512, Hsz,
                         g_q2[kh] + n0, Hsz, 32, sbuf);
            } else {
                int idx = bx - 32, jt = idx >> 1, kh = idx & 1, n0 = jt * 64;
                gemm64cp(g_h + kh * 512, Hsz,
                         W_hh + (size_t)n0 * Hsz + kh * 512, Hsz,
                         g_gh2[kh] + n0, 3 * Hsz, 32, sbuf);
            }
        }
        gbar();

        // ---- Phase BC: scores + softmax + ctx, block b owns batch b ----
        if (bx < Bsz) {
            int b = bx;
            float* qs = sbuf;            // 1024
            float* va = sbuf + 1024;     // 1024
            float* sc = sbuf + 2048;     // 64
            float* ws = sbuf + 2112;     // 64
            for (int j = tid; j < Hsz; j += NTHR) {
                qs[j] = g_q2[0][b * Hsz + j] + g_q2[1][b * Hsz + j];
                va[j] = Va[j];
            }
            __syncthreads();
            int w = tid >> 5, lane = tid & 31;
#pragma unroll
            for (int si = 0; si < 8; si++) {
                int s = w * 8 + si;
                const float* kp = g_keysU + (size_t)(b * Ssz + s) * Hsz;
                float acc = 0.f;
#pragma unroll 8
                for (int jj = 0; jj < 32; jj++) {
                    int j = lane + jj * 32;
                    acc += va[j] * tanh_fast(qs[j] + kp[j]);
                }
#pragma unroll
                for (int o = 16; o > 0; o >>= 1) acc += __shfl_xor_sync(0xffffffffu, acc, o);
                if (lane == 0) sc[s] = acc;
            }
            __syncthreads();
            if (w == 0) {
                float v0 = sc[lane], v1 = sc[lane + 32];
                float m = fmaxf(v0, v1);
#pragma unroll
                for (int o = 16; o > 0; o >>= 1) m = fmaxf(m, __shfl_xor_sync(0xffffffffu, m, o));
                float e0 = __expf(v0 - m), e1 = __expf(v1 - m);
                float ssum = e0 + e1;
#pragma unroll
                for (int o = 16; o > 0; o >>= 1) ssum += __shfl_xor_sync(0xffffffffu, ssum, o);
                float inv = __fdividef(1.f, ssum);
                ws[lane] = e0 * inv;
                ws[lane + 32] = e1 * inv;
            }
            __syncthreads();
            if (tid < Ssz) out_attn[(size_t)b * Tsz * Ssz + t * Ssz + tid] = ws[tid];
            float c0 = 0.f, c1 = 0.f, c2 = 0.f, c3 = 0.f;
            const float* ep = enc + (size_t)b * Ssz * Hsz + tid;
#pragma unroll 4
            for (int s = 0; s < Ssz; s++) {
                float wv = ws[s];
                const float* row = ep + (size_t)s * Hsz;
                c0 += wv * row[0];
                c1 += wv * row[256];
                c2 += wv * row[512];
                c3 += wv * row[768];
            }
            g_ctx[b * Hsz + tid]       = c0;
            g_ctx[b * Hsz + tid + 256] = c1;
            g_ctx[b * Hsz + tid + 512] = c2;
            g_ctx[b * Hsz + tid + 768] = c3;
        }
        gbar();

        // ---- Phase D: gi_ctx = ctx @ W_ih[:, H:2H]^T  (96 part-tiles, K=512)
        if (bx < 96) {
            int jt = bx >> 1, kh = bx & 1, n0 = jt * 64;
            gemm64cp(g_ctx + kh * 512, Hsz,
                     W_ih + (size_t)n0 * (2 * Hsz) + Hsz + kh * 512, 2 * Hsz,
                     g_gc2[kh] + n0, 3 * Hsz, 32, sbuf);
        }
        gbar();

        // ---- Phase E: gates + h update ----
        {
            const float* giE = g_giE + (size_t)t * Bsz * 3 * Hsz;
            for (int i = bx * NTHR + tid; i < Bsz * Hsz; i += NBLK * NTHR) {
                int b = i >> 10, j = i & (Hsz - 1);
                size_t base3 = (size_t)b * 3 * Hsz;
                float ir = giE[base3 + j]            + g_gc2[0][base3 + j]            + g_gc2[1][base3 + j]            + b_ih[j];
                float iz = giE[base3 + Hsz + j]      + g_gc2[0][base3 + Hsz + j]      + g_gc2[1][base3 + Hsz + j]      + b_ih[Hsz + j];
                float in = giE[base3 + 2 * Hsz + j]  + g_gc2[0][base3 + 2 * Hsz + j]  + g_gc2[1][base3 + 2 * Hsz + j]  + b_ih[2 * Hsz + j];
                float hr = g_gh2[0][base3 + j]            + g_gh2[1][base3 + j]            + b_hh[j];
                float hz = g_gh2[0][base3 + Hsz + j]      + g_gh2[1][base3 + Hsz + j]      + b_hh[Hsz + j];
                float hn = g_gh2[0][base3 + 2 * Hsz + j]  + g_gh2[1][base3 + 2 * Hsz + j]  + b_hh[2 * Hsz + j];
                float rr = fsigmoid(ir + hr);
                float zz = fsigmoid(iz + hz);
                float nn = ftanh(in + rr * hn);
                float hp = g_h[i];
                float hnew = (1.f - zz) * nn + zz * hp;
                g_h[i] = hnew;
                g_hall[((size_t)t * Bsz + b) * Hsz + j] = __float2bfloat16(hnew);
            }
        }
        gbar();
    }

    for (int i = bx * NTHR + tid; i < Bsz * Hsz; i += NBLK * NTHR)
        out_hid[i] = g_h[i];
}

// ---------------- batched output projection: logits = Hall @ Wout^T + b_out ----------------
__global__ __launch_bounds__(256) void k_gemm_out(const float* __restrict__ b_out,
                                                  float* __restrict__ out) {
    const int K = Hsz;
    __shared__ __nv_bfloat16 As[2][128 * 40];
    __shared__ __nv_bfloat16 Bs[2][128 * 40];
    int m0 = blockIdx.y * 128, n0 = blockIdx.x * 128;
    int tid = threadIdx.x;
    int warp = tid >> 5, lane = tid & 31;
    int wm = warp >> 2, wn = warp & 3;
    int lrow = tid >> 2;
    int kch = (tid & 3) * 8;

    wmma::fragment<wmma::accumulator, 16, 16, 16, float> acc[4][2];
#pragma unroll
    for (int i = 0; i < 4; i++)
#pragma unroll
        for (int j = 0; j < 2; j++) wmma::fill_fragment(acc[i][j], 0.f);

    const __nv_bfloat16* Ag = g_hall + (size_t)(m0 + lrow) * K + kch;
    const __nv_bfloat16* Bg = g_wout + (size_t)(n0 + lrow) * K + kch;

    uint4 ra0, ra1, rb0, rb1;
    ra0 = *(const uint4*)(Ag);            ra1 = *(const uint4*)(Ag + 64 * K);
    rb0 = *(const uint4*)(Bg);            rb1 = *(const uint4*)(Bg + 64 * K);
    *(uint4*)&As[0][lrow * 40 + kch] = ra0;
    *(uint4*)&As[0][(lrow + 64) * 40 + kch] = ra1;
    *(uint4*)&Bs[0][lrow * 40 + kch] = rb0;
    *(uint4*)&Bs[0][(lrow + 64) * 40 + kch] = rb1;
    __syncthreads();

    const int NKT = K / 32;
    for (int kt = 0; kt < NKT; kt++) {
        int cur = kt & 1, nxt = cur ^ 1;
        if (kt + 1 < NKT) {
            const __nv_bfloat16* a = Ag + (kt + 1) * 32;
            ra0 = *(const uint4*)(a);     ra1 = *(const uint4*)(a + 64 * K);
            const __nv_bfloat16* bp = Bg + (kt + 1) * 32;
            rb0 = *(const uint4*)(bp);    rb1 = *(const uint4*)(bp + 64 * K);
        }
#pragma unroll
        for (int ks = 0; ks < 2; ks++) {
            wmma::fragment<wmma::matrix_a, 16, 16, 16, __nv_bfloat16, wmma::row_major> af[4];
            wmma::fragment<wmma::matrix_b, 16, 16, 16, __nv_bfloat16, wmma::col_major> bf[2];
#pragma unroll
            for (int i = 0; i < 4; i++)
                wmma::load_matrix_sync(af[i], &As[cur][(wm * 64 + i * 16) * 40 + ks * 16], 40);
#pragma unroll
            for (int j = 0; j < 2; j++)
                wmma::load_matrix_sync(bf[j], &Bs[cur][(wn * 32 + j * 16) * 40 + ks * 16], 40);
#pragma unroll
            for (int i = 0; i < 4; i++)
#pragma unroll
                for (int j = 0; j < 2; j++)
                    wmma::mma_sync(acc[i][j], af[i], bf[j], acc[i][j]);
        }
        if (kt + 1 < NKT) {
            *(uint4*)&As[nxt][lrow * 40 + kch] = ra0;
            *(uint4*)&As[nxt][(lrow + 64) * 40 + kch] = ra1;
            *(uint4*)&Bs[nxt][lrow * 40 + kch] = rb0;
            *(uint4*)&Bs[nxt][(lrow + 64) * 40 + kch] = rb1;
        }
        __syncthreads();
    }

    float* stage = (float*)&As[0][0];
    float* sp = stage + warp * 320;
#pragma unroll
    for (int i = 0; i < 4; i++) {
#pragma unroll
        for (int j = 0; j < 2; j++) {
            wmma::store_matrix_sync(sp, acc[i][j], 20, wmma::mem_row_major);
            __syncwarp();
            int gr0 = m0 + wm * 64 + i * 16;
            int gc0 = n0 + wn * 32 + j * 16;
            for (int e = lane; e < 256; e += 32) {
                int r = e >> 4, cc = e & 15;
                int gr = gr0 + r, gc = gc0 + cc;
                int bb = gr & 63, tt = gr >> 6;
                out[(size_t)(bb * Tsz + tt) * Vsz + gc] = sp[r * 20 + cc] + b_out[gc];
            }
            __syncwarp();
        }
    }
}

// ---------------- in-place log_softmax (float4) ----------------
__global__ __launch_bounds__(256) void k_logsoftmax(float* __restrict__ out) {
    int row = blockIdx.x;
    float4* p4 = (float4*)(out + (size_t)row * Vsz);
    const int N4 = Vsz / 4;   // 8000
    int tid = threadIdx.x;
    float m = -1e30f, s = 0.f;
    for (int j = tid; j < N4; j += 256) {
        float4 v = p4[j];
        float vm = fmaxf(fmaxf(v.x, v.y), fmaxf(v.z, v.w));
        if (vm > m) { s = s * __expf(m - vm); m = vm; }
        s += __expf(v.x - m) + __expf(v.y - m) + __expf(v.z - m) + __expf(v.w - m);
    }
    __shared__ float sm[256], ss[256];
    sm[tid] = m; ss[tid] = s;
    __syncthreads();
    for (int o = 128; o > 0; o >>= 1) {
        if (tid < o) {
            float m2 = sm[tid + o], s2 = ss[tid + o];
            float mm = fmaxf(sm[tid], m2);
            ss[tid] = ss[tid] * __expf(sm[tid] - mm) + s2 * __expf(m2 - mm);
            sm[tid] = mm;
        }
        __syncthreads();
    }
    float L = sm[0] + logf(ss[0]);
    for (int j = tid; j < N4; j += 256) {
        float4 v = p4[j];
        v.x -= L; v.y -= L; v.z -= L; v.w -= L;
        p4[j] = v;
    }
}

// ---------------- launch ----------------
extern "C" void kernel_launch(void* const* d_in, const int* in_sizes, int n_in,
                              void* d_out, int out_size) {
    const float* enc_out = (const float*)d_in[0];
    const float* enc_hid = (const float*)d_in[1];
    const int*   target  = (const int*)d_in[2];
    const float* embedding = (const float*)d_in[3];
    const float* Wa  = (const float*)d_in[4];
    const float* ba  = (const float*)d_in[5];
    const float* Ua  = (const float*)d_in[6];
    const float* bu  = (const float*)d_in[7];
    const float* Va  = (const float*)d_in[8];
    // d_in[9] = bv : softmax shift-invariant, unused
    const float* W_ih = (const float*)d_in[10];
    const float* W_hh = (const float*)d_in[11];
    const float* b_ih = (const float*)d_in[12];
    const float* b_hh = (const float*)d_in[13];
    const float* W_out = (const float*)d_in[14];
    const float* b_out = (const float*)d_in[15];

    float* out = (float*)d_out;
    float* out_dec  = out;                                        // [B,T,V]
    float* out_hid  = out + (size_t)Bsz * Tsz * Vsz;              // [1,B,H]
    float* out_attn = out_hid + (size_t)Bsz * Hsz;                // [B,T,S]

    // init
    k_embed<<<Tsz * Bsz, 256>>>(target, embedding);
    k_init_h<<<(Bsz * Hsz + 255) / 256, 256>>>(enc_hid);
    k_wout_conv<<<2048, 256>>>(W_out);
    {
        dim3 grid(Hsz / 64, (Bsz * Ssz) / 64);
        k_gemm_keysu<<<grid, NTHR>>>(enc_out, Ua);
    }
    k_keysu_bias<<<4096, 256>>>(ba, bu);
    {
        dim3 grid(48, Tsz);
        k_gemm_giemb<<<grid, NTHR>>>(W_ih);
    }

    // full recurrence in one launch
    k_persist<<<NBLK, NTHR>>>(enc_out, Wa, Va, W_ih, W_hh, b_ih, b_hh,
                              out_attn, out_hid);

    // output projection + log_softmax
    {
        dim3 grid(Vsz / 128, (Tsz * Bsz) / 128);
        k_gemm_out<<<grid, 256>>>(b_out, out_dec);
    }
    k_logsoftmax<<<Tsz * Bsz, 256>>>(out_dec);
}